// round 1
// baseline (speedup 1.0000x reference)
#include <cuda_runtime.h>
#include <cuda_bf16.h>
#include <math.h>

// ---------------------------------------------------------------------------
// Shapes
//  x (1024,4,84,84) -> conv1 5x5 p2 -> pool -> relu : a1 (1024,32,42,42)
//  conv2 5x5 p1 -> pool -> relu : a2 (1024,32,20,20)
//  conv3 4x4 p1 -> pool -> relu : a3 (1024,64,9,9)
//  conv4 3x3 p1 -> pool -> relu -> flatten : feat (1024,1024)
//  LSTM T=16 B=64 H=512, gates i,f,g,o ; heads -> out (1024,19) + hT + cT
// ---------------------------------------------------------------------------

#define NSAMP 1024

// scratch (device globals: allocation-free rule)
__device__ float g_a1[NSAMP * 32 * 42 * 42];   // 231 MB
__device__ float g_a2[NSAMP * 32 * 20 * 20];
__device__ float g_a3[NSAMP * 64 * 9 * 9];
__device__ float g_feat[NSAMP * 1024];
__device__ float g_gx[NSAMP * 2048];           // feat @ W_ih^T (all steps)
__device__ float g_ghh[2 * 64 * 2048];         // split-K=2 partials of h @ W_hh^T
__device__ float g_h[64 * 512];
__device__ float g_c[64 * 512];
__device__ float g_hidden[NSAMP * 512];

// ---------------------------------------------------------------------------
// conv1: per-sample block. smem: padded input 4x88x88 + all weights (136704 B)
// ---------------------------------------------------------------------------
__global__ void __launch_bounds__(512) conv1_kernel(const float* __restrict__ x,
                                                    const float* __restrict__ w,
                                                    const float* __restrict__ bias) {
    extern __shared__ float sm[];
    float* s_in = sm;               // 4*88*88 = 30976
    float* s_w  = sm + 4 * 88 * 88; // 3200
    const int n = blockIdx.x;

    for (int i = threadIdx.x; i < 4 * 88 * 88; i += blockDim.x) {
        int ic = i / (88 * 88);
        int rem = i % (88 * 88);
        int r = rem / 88, c = rem % 88;
        int y = r - 2, xx = c - 2;
        float v = 0.f;
        if ((unsigned)y < 84u && (unsigned)xx < 84u)
            v = x[((n * 4 + ic) * 84 + y) * 84 + xx];
        s_in[i] = v;
    }
    for (int i = threadIdx.x; i < 3200; i += blockDim.x) s_w[i] = w[i];
    __syncthreads();

    for (int p = threadIdx.x; p < 16 * 42 * 42; p += blockDim.x) {
        int oc = p / (42 * 42);
        int rem = p % (42 * 42);
        int py = rem / 42, px = rem % 42;
        int oc2 = oc + 16;
        float acc0[2][2] = {{0.f,0.f},{0.f,0.f}};
        float acc1[2][2] = {{0.f,0.f},{0.f,0.f}};
        #pragma unroll
        for (int ic = 0; ic < 4; ic++) {
            float wa[25], wb[25];
            #pragma unroll
            for (int i = 0; i < 25; i++) {
                wa[i] = s_w[(oc  * 4 + ic) * 25 + i];
                wb[i] = s_w[(oc2 * 4 + ic) * 25 + i];
            }
            const float* sp = s_in + ic * 88 * 88 + (2 * py) * 88 + 2 * px;
            #pragma unroll
            for (int r = 0; r < 6; r++) {
                float v[6];
                #pragma unroll
                for (int c = 0; c < 6; c++) v[c] = sp[r * 88 + c];
                #pragma unroll
                for (int dy = 0; dy < 2; dy++) {
                    int ky = r - dy;
                    if (ky >= 0 && ky < 5) {
                        #pragma unroll
                        for (int kx = 0; kx < 5; kx++) {
                            float w0 = wa[ky * 5 + kx], w1v = wb[ky * 5 + kx];
                            acc0[dy][0] += w0  * v[kx];
                            acc0[dy][1] += w0  * v[kx + 1];
                            acc1[dy][0] += w1v * v[kx];
                            acc1[dy][1] += w1v * v[kx + 1];
                        }
                    }
                }
            }
        }
        float m0 = fmaxf(fmaxf(acc0[0][0], acc0[0][1]), fmaxf(acc0[1][0], acc0[1][1])) + bias[oc];
        float m1 = fmaxf(fmaxf(acc1[0][0], acc1[0][1]), fmaxf(acc1[1][0], acc1[1][1])) + bias[oc2];
        g_a1[((n * 32 + oc ) * 42 + py) * 42 + px] = fmaxf(m0, 0.f);
        g_a1[((n * 32 + oc2) * 42 + py) * 42 + px] = fmaxf(m1, 0.f);
    }
}

// ---------------------------------------------------------------------------
// conv2: block = (sample, 5-pooled-row strip). smem: 32x14x44 rows + all w (181248 B)
// ---------------------------------------------------------------------------
__global__ void __launch_bounds__(320) conv2_kernel(const float* __restrict__ w,
                                                    const float* __restrict__ bias) {
    extern __shared__ float sm[];
    float* s_in = sm;                // 32*14*44 = 19712
    float* s_w  = sm + 32 * 14 * 44; // 25600
    const int n = blockIdx.x;
    const int py0 = 5 * blockIdx.y;

    for (int i = threadIdx.x; i < 32 * 14 * 44; i += blockDim.x) {
        int ic = i / 616;
        int rem = i % 616;
        int rr = rem / 44, cc = rem % 44;
        int y = 2 * py0 - 1 + rr;
        int xx = cc - 1;
        float v = 0.f;
        if ((unsigned)y < 42u && (unsigned)xx < 42u)
            v = g_a1[((n * 32 + ic) * 42 + y) * 42 + xx];
        s_in[i] = v;
    }
    for (int i = threadIdx.x; i < 25600; i += blockDim.x) s_w[i] = w[i];
    __syncthreads();

    for (int p = threadIdx.x; p < 16 * 5 * 20; p += blockDim.x) {
        int oc = p / 100;
        int rem = p % 100;
        int lpy = rem / 20, px = rem % 20;
        int oc2 = oc + 16;
        float acc0[2][2] = {{0.f,0.f},{0.f,0.f}};
        float acc1[2][2] = {{0.f,0.f},{0.f,0.f}};
        #pragma unroll 4
        for (int ic = 0; ic < 32; ic++) {
            float wa[25], wb[25];
            #pragma unroll
            for (int i = 0; i < 25; i++) {
                wa[i] = s_w[(oc  * 32 + ic) * 25 + i];
                wb[i] = s_w[(oc2 * 32 + ic) * 25 + i];
            }
            const float* sp = s_in + ic * 616 + (2 * lpy) * 44 + 2 * px;
            #pragma unroll
            for (int r = 0; r < 6; r++) {
                float v[6];
                #pragma unroll
                for (int c = 0; c < 6; c++) v[c] = sp[r * 44 + c];
                #pragma unroll
                for (int dy = 0; dy < 2; dy++) {
                    int ky = r - dy;
                    if (ky >= 0 && ky < 5) {
                        #pragma unroll
                        for (int kx = 0; kx < 5; kx++) {
                            float w0 = wa[ky * 5 + kx], w1v = wb[ky * 5 + kx];
                            acc0[dy][0] += w0  * v[kx];
                            acc0[dy][1] += w0  * v[kx + 1];
                            acc1[dy][0] += w1v * v[kx];
                            acc1[dy][1] += w1v * v[kx + 1];
                        }
                    }
                }
            }
        }
        int py = py0 + lpy;
        float m0 = fmaxf(fmaxf(acc0[0][0], acc0[0][1]), fmaxf(acc0[1][0], acc0[1][1])) + bias[oc];
        float m1 = fmaxf(fmaxf(acc1[0][0], acc1[0][1]), fmaxf(acc1[1][0], acc1[1][1])) + bias[oc2];
        g_a2[((n * 32 + oc ) * 20 + py) * 20 + px] = fmaxf(m0, 0.f);
        g_a2[((n * 32 + oc2) * 20 + py) * 20 + px] = fmaxf(m1, 0.f);
    }
}

// ---------------------------------------------------------------------------
// conv3: per-sample block. smem: 32x21x21 + all w (187520 B). 4x4 k, pad 1.
// ---------------------------------------------------------------------------
__global__ void __launch_bounds__(512) conv3_kernel(const float* __restrict__ w,
                                                    const float* __restrict__ bias) {
    extern __shared__ float sm[];
    float* s_in = sm;            // 32*441 = 14112
    float* s_w  = sm + 14112;    // 32768
    const int n = blockIdx.x;

    for (int i = threadIdx.x; i < 14112; i += blockDim.x) {
        int ic = i / 441;
        int rem = i % 441;
        int r = rem / 21, c = rem % 21;
        int y = r - 1, xx = c - 1;
        float v = 0.f;
        if ((unsigned)y < 20u && (unsigned)xx < 20u)
            v = g_a2[((n * 32 + ic) * 20 + y) * 20 + xx];
        s_in[i] = v;
    }
    for (int i = threadIdx.x; i < 32768; i += blockDim.x) s_w[i] = w[i];
    __syncthreads();

    for (int p = threadIdx.x; p < 32 * 81; p += blockDim.x) {
        int oc = p / 81;
        int rem = p % 81;
        int py = rem / 9, px = rem % 9;
        int oc2 = oc + 32;
        float acc0[2][2] = {{0.f,0.f},{0.f,0.f}};
        float acc1[2][2] = {{0.f,0.f},{0.f,0.f}};
        #pragma unroll 4
        for (int ic = 0; ic < 32; ic++) {
            float wa[16], wb[16];
            #pragma unroll
            for (int i = 0; i < 16; i++) {
                wa[i] = s_w[(oc  * 32 + ic) * 16 + i];
                wb[i] = s_w[(oc2 * 32 + ic) * 16 + i];
            }
            const float* sp = s_in + ic * 441 + (2 * py) * 21 + 2 * px;
            #pragma unroll
            for (int r = 0; r < 5; r++) {
                float v[5];
                #pragma unroll
                for (int c = 0; c < 5; c++) v[c] = sp[r * 21 + c];
                #pragma unroll
                for (int dy = 0; dy < 2; dy++) {
                    int ky = r - dy;
                    if (ky >= 0 && ky < 4) {
                        #pragma unroll
                        for (int kx = 0; kx < 4; kx++) {
                            float w0 = wa[ky * 4 + kx], w1v = wb[ky * 4 + kx];
                            acc0[dy][0] += w0  * v[kx];
                            acc0[dy][1] += w0  * v[kx + 1];
                            acc1[dy][0] += w1v * v[kx];
                            acc1[dy][1] += w1v * v[kx + 1];
                        }
                    }
                }
            }
        }
        float m0 = fmaxf(fmaxf(acc0[0][0], acc0[0][1]), fmaxf(acc0[1][0], acc0[1][1])) + bias[oc];
        float m1 = fmaxf(fmaxf(acc1[0][0], acc1[0][1]), fmaxf(acc1[1][0], acc1[1][1])) + bias[oc2];
        g_a3[((n * 64 + oc ) * 9 + py) * 9 + px] = fmaxf(m0, 0.f);
        g_a3[((n * 64 + oc2) * 9 + py) * 9 + px] = fmaxf(m1, 0.f);
    }
}

// ---------------------------------------------------------------------------
// conv4: per-sample block. smem: 64x11x12 + all w (181248 B). 3x3 k, pad 1.
// Writes flattened features directly.
// ---------------------------------------------------------------------------
__global__ void __launch_bounds__(512) conv4_kernel(const float* __restrict__ w,
                                                    const float* __restrict__ bias) {
    extern __shared__ float sm[];
    float* s_in = sm;           // 64*132 = 8448
    float* s_w  = sm + 8448;    // 36864
    const int n = blockIdx.x;

    for (int i = threadIdx.x; i < 8448; i += blockDim.x) {
        int ic = i / 132;
        int rem = i % 132;
        int r = rem / 12, c = rem % 12;
        int y = r - 1, xx = c - 1;
        float v = 0.f;
        if ((unsigned)y < 9u && (unsigned)xx < 9u)
            v = g_a3[((n * 64 + ic) * 9 + y) * 9 + xx];
        s_in[i] = v;
    }
    for (int i = threadIdx.x; i < 36864; i += blockDim.x) s_w[i] = w[i];
    __syncthreads();

    for (int p = threadIdx.x; p < 32 * 16; p += blockDim.x) {
        int oc = p / 16;
        int rem = p % 16;
        int py = rem / 4, px = rem % 4;
        int oc2 = oc + 32;
        float acc0[2][2] = {{0.f,0.f},{0.f,0.f}};
        float acc1[2][2] = {{0.f,0.f},{0.f,0.f}};
        #pragma unroll 8
        for (int ic = 0; ic < 64; ic++) {
            float wa[9], wb[9];
            #pragma unroll
            for (int i = 0; i < 9; i++) {
                wa[i] = s_w[(oc  * 64 + ic) * 9 + i];
                wb[i] = s_w[(oc2 * 64 + ic) * 9 + i];
            }
            const float* sp = s_in + ic * 132 + (2 * py) * 12 + 2 * px;
            #pragma unroll
            for (int r = 0; r < 4; r++) {
                float v[4];
                #pragma unroll
                for (int c = 0; c < 4; c++) v[c] = sp[r * 12 + c];
                #pragma unroll
                for (int dy = 0; dy < 2; dy++) {
                    int ky = r - dy;
                    if (ky >= 0 && ky < 3) {
                        #pragma unroll
                        for (int kx = 0; kx < 3; kx++) {
                            float w0 = wa[ky * 3 + kx], w1v = wb[ky * 3 + kx];
                            acc0[dy][0] += w0  * v[kx];
                            acc0[dy][1] += w0  * v[kx + 1];
                            acc1[dy][0] += w1v * v[kx];
                            acc1[dy][1] += w1v * v[kx + 1];
                        }
                    }
                }
            }
        }
        float m0 = fmaxf(fmaxf(acc0[0][0], acc0[0][1]), fmaxf(acc0[1][0], acc0[1][1])) + bias[oc];
        float m1 = fmaxf(fmaxf(acc1[0][0], acc1[0][1]), fmaxf(acc1[1][0], acc1[1][1])) + bias[oc2];
        g_feat[n * 1024 + oc  * 16 + py * 4 + px] = fmaxf(m0, 0.f);
        g_feat[n * 1024 + oc2 * 16 + py * 4 + px] = fmaxf(m1, 0.f);
    }
}

// ---------------------------------------------------------------------------
// GEMM  C[M,N] = A[M,K] @ B[N,K]^T  (both K-contiguous). Optional per-row
// (1 - done) mask on A, optional split-K across gridDim.z (partials to
// separate C slabs).
// ---------------------------------------------------------------------------
template <int BM, int BN, int BK, int TM, int TN, bool MASK, bool SPLITK>
__device__ __forceinline__ void gemm_body(const float* __restrict__ A,
                                          const float* __restrict__ B,
                                          float* __restrict__ C,
                                          int M, int N, int K,
                                          const float* __restrict__ dvec) {
    __shared__ float As[BK][BM + 4];
    __shared__ float Bs[BK][BN + 4];
    constexpr int NT = (BM / TM) * (BN / TN);
    const int tid = threadIdx.x;
    const int tx = tid % (BN / TN);
    const int ty = tid / (BN / TN);
    const int m0 = blockIdx.y * BM;
    const int n0 = blockIdx.x * BN;
    int kBeg = 0, kEnd = K;
    if (SPLITK) {
        int kc = K / gridDim.z;
        kBeg = blockIdx.z * kc;
        kEnd = kBeg + kc;
        C += (size_t)blockIdx.z * M * N;
    }
    float acc[TM][TN];
    #pragma unroll
    for (int i = 0; i < TM; i++)
        #pragma unroll
        for (int j = 0; j < TN; j++) acc[i][j] = 0.f;

    for (int kk = kBeg; kk < kEnd; kk += BK) {
        for (int i = tid; i < BM * BK; i += NT) {
            int r = i / BK, c = i % BK;
            float v = A[(m0 + r) * K + kk + c];
            if (MASK) v *= (1.0f - dvec[m0 + r]);
            As[c][r] = v;
        }
        for (int i = tid; i < BN * BK; i += NT) {
            int r = i / BK, c = i % BK;
            Bs[c][r] = B[(n0 + r) * K + kk + c];
        }
        __syncthreads();
        #pragma unroll
        for (int k = 0; k < BK; k++) {
            float a[TM], b[TN];
            #pragma unroll
            for (int i = 0; i < TM; i++) a[i] = As[k][ty * TM + i];
            #pragma unroll
            for (int j = 0; j < TN; j++) b[j] = Bs[k][tx * TN + j];
            #pragma unroll
            for (int i = 0; i < TM; i++)
                #pragma unroll
                for (int j = 0; j < TN; j++) acc[i][j] += a[i] * b[j];
        }
        __syncthreads();
    }
    #pragma unroll
    for (int i = 0; i < TM; i++)
        #pragma unroll
        for (int j = 0; j < TN; j++)
            C[(size_t)(m0 + ty * TM + i) * N + n0 + tx * TN + j] = acc[i][j];
}

__global__ void __launch_bounds__(256) gemm_gx_kernel(const float* __restrict__ W_ih) {
    gemm_body<64, 64, 16, 4, 4, false, false>(g_feat, W_ih, g_gx, 1024, 2048, 1024, nullptr);
}

__global__ void __launch_bounds__(256) gemm_hh_kernel(const float* __restrict__ W_hh,
                                                      const float* __restrict__ done, int t) {
    gemm_body<64, 32, 16, 4, 2, true, true>(g_h, W_hh, g_ghh, 64, 2048, 512, done + t * 64);
}

// ---------------------------------------------------------------------------
// LSTM elementwise update (one step)
// ---------------------------------------------------------------------------
__device__ __forceinline__ float sigm(float x) { return 1.f / (1.f + expf(-x)); }

__global__ void lstm_update_kernel(const float* __restrict__ b_ih,
                                   const float* __restrict__ b_hh,
                                   const float* __restrict__ done, int t) {
    int idx = blockIdx.x * blockDim.x + threadIdx.x;  // 64*512
    if (idx >= 64 * 512) return;
    int b = idx / 512, j = idx % 512;
    int n = t * 64 + b;
    const float* gx = g_gx + (size_t)n * 2048;
    const float* g1 = g_ghh + (size_t)b * 2048;
    const float* g2 = g_ghh + 64 * 2048 + (size_t)b * 2048;

    float gi = gx[j]        + g1[j]        + g2[j]        + b_ih[j]        + b_hh[j];
    float gf = gx[512 + j]  + g1[512 + j]  + g2[512 + j]  + b_ih[512 + j]  + b_hh[512 + j];
    float gg = gx[1024 + j] + g1[1024 + j] + g2[1024 + j] + b_ih[1024 + j] + b_hh[1024 + j];
    float go = gx[1536 + j] + g1[1536 + j] + g2[1536 + j] + b_ih[1536 + j] + b_hh[1536 + j];

    float m = 1.0f - done[n];
    float c = g_c[idx] * m;
    float cn = sigm(gf) * c + sigm(gi) * tanhf(gg);
    float hn = sigm(go) * tanhf(cn);
    g_c[idx] = cn;
    g_h[idx] = hn;
    g_hidden[(size_t)n * 512 + j] = hn;
}

// ---------------------------------------------------------------------------
// heads: one warp per row n; 19 outputs (18 logits + 1 value)
// ---------------------------------------------------------------------------
__global__ void __launch_bounds__(256) head_kernel(const float* __restrict__ Wa,
                                                   const float* __restrict__ ba,
                                                   const float* __restrict__ Wc,
                                                   const float* __restrict__ bc,
                                                   float* __restrict__ out) {
    int warp = threadIdx.x / 32, lane = threadIdx.x % 32;
    int n = blockIdx.x * 8 + warp;
    float h[16];
    #pragma unroll
    for (int i = 0; i < 16; i++) h[i] = g_hidden[(size_t)n * 512 + i * 32 + lane];
    for (int j = 0; j < 19; j++) {
        const float* w = (j < 18) ? (Wa + j * 512) : Wc;
        float s = 0.f;
        #pragma unroll
        for (int i = 0; i < 16; i++) s += h[i] * w[i * 32 + lane];
        #pragma unroll
        for (int o = 16; o; o >>= 1) s += __shfl_xor_sync(0xffffffffu, s, o);
        if (lane == 0) out[n * 19 + j] = s + ((j < 18) ? ba[j] : bc[0]);
    }
}

__global__ void init_state_kernel(const float* __restrict__ h0, const float* __restrict__ c0) {
    int idx = blockIdx.x * blockDim.x + threadIdx.x;
    if (idx < 64 * 512) { g_h[idx] = h0[idx]; g_c[idx] = c0[idx]; }
}

__global__ void copy_out_kernel(float* __restrict__ out) {
    int idx = blockIdx.x * blockDim.x + threadIdx.x;
    if (idx < 64 * 512) {
        out[19456 + idx] = g_h[idx];
        out[19456 + 32768 + idx] = g_c[idx];
    }
}

// ---------------------------------------------------------------------------
extern "C" void kernel_launch(void* const* d_in, const int* in_sizes, int n_in,
                              void* d_out, int out_size) {
    const float* x    = (const float*)d_in[0];
    const float* done = (const float*)d_in[1];
    const float* h0   = (const float*)d_in[2];
    const float* c0   = (const float*)d_in[3];
    const float* w1   = (const float*)d_in[4];
    const float* b1   = (const float*)d_in[5];
    const float* w2   = (const float*)d_in[6];
    const float* b2   = (const float*)d_in[7];
    const float* w3   = (const float*)d_in[8];
    const float* b3   = (const float*)d_in[9];
    const float* w4   = (const float*)d_in[10];
    const float* b4   = (const float*)d_in[11];
    const float* W_ih = (const float*)d_in[12];
    const float* W_hh = (const float*)d_in[13];
    const float* b_ih = (const float*)d_in[14];
    const float* b_hh = (const float*)d_in[15];
    const float* Wa   = (const float*)d_in[16];
    const float* ba   = (const float*)d_in[17];
    const float* Wc   = (const float*)d_in[18];
    const float* bc   = (const float*)d_in[19];
    float* out = (float*)d_out;

    const int SM1 = (4 * 88 * 88 + 3200) * 4;      // 136704
    const int SM2 = (32 * 14 * 44 + 25600) * 4;    // 181248
    const int SM3 = (14112 + 32768) * 4;           // 187520
    const int SM4 = (8448 + 36864) * 4;            // 181248
    cudaFuncSetAttribute(conv1_kernel, cudaFuncAttributeMaxDynamicSharedMemorySize, SM1);
    cudaFuncSetAttribute(conv2_kernel, cudaFuncAttributeMaxDynamicSharedMemorySize, SM2);
    cudaFuncSetAttribute(conv3_kernel, cudaFuncAttributeMaxDynamicSharedMemorySize, SM3);
    cudaFuncSetAttribute(conv4_kernel, cudaFuncAttributeMaxDynamicSharedMemorySize, SM4);

    init_state_kernel<<<128, 256>>>(h0, c0);

    conv1_kernel<<<NSAMP, 512, SM1>>>(x, w1, b1);
    conv2_kernel<<<dim3(NSAMP, 4), 320, SM2>>>(w2, b2);
    conv3_kernel<<<NSAMP, 512, SM3>>>(w3, b3);
    conv4_kernel<<<NSAMP, 512, SM4>>>(w4, b4);

    // input-side gate GEMM for all timesteps at once
    gemm_gx_kernel<<<dim3(2048 / 64, 1024 / 64, 1), 256>>>(W_ih);

    // sequential recurrence
    for (int t = 0; t < 16; t++) {
        gemm_hh_kernel<<<dim3(2048 / 32, 1, 2), 256>>>(W_hh, done, t);
        lstm_update_kernel<<<128, 256>>>(b_ih, b_hh, done, t);
    }

    head_kernel<<<NSAMP / 8, 256>>>(Wa, ba, Wc, bc, out);
    copy_out_kernel<<<128, 256>>>(out);
}